// round 5
// baseline (speedup 1.0000x reference)
#include <cuda_runtime.h>

// PeptidePocketConvLayer — GB300 sm_103a
//
// Inputs (metadata order):
//   d_in[0]: peptide_encoding  f32 [B, 15, 20]
//   d_in[1]: pocket_encoding   i32 [B, 34]
//   d_in[2]: kernel            f32 [20, 9]
// Output: f32 [B, 34, 28]
//
// Structure exploited:
//  - pocket mask periodic with period 9 -> only 9 distinct aggregates/batch
//  - peptide rows 9..14 never referenced
//  - full conv via zero-padded shared rows (logical indices -8..27)
//  - kernel table (20x9) staged raw per block, padded to stride 12 so a
//    filter row is 2x LDS.128 + 1 LDS; no per-pocket gather phase.

#define NPOCK      34
#define OUT_F4     238          // 34*28/4 float4 per batch
#define PEP_STRIDE 300          // 15*20 floats per batch
#define AGG_STRIDE 36           // padded row: logical a-index -8..27
#define KER_STRIDE 12           // padded kernel row (48B, 16B-aligned)

__global__ __launch_bounds__(256, 8)
void pep_pocket_conv_kernel(const float* __restrict__ pep,
                            const int*   __restrict__ pock,
                            const float* __restrict__ ker,
                            float*       __restrict__ out)
{
    __shared__ __align__(16) float sPep[180];               // rows 0..8 x 20
    __shared__ __align__(16) float sAgg[9 * AGG_STRIDE];    // 324
    __shared__ __align__(16) float sKer[20 * KER_STRIDE];   // 240 (cols 9..11 unused)
    __shared__ int   sId[NPOCK];

    const int b = blockIdx.x;
    const int t = threadIdx.x;

    // ---- stage: warps 0-1 do pocket ids + peptide; warps 2-7 do kernel table ----
    if (t < NPOCK) {
        sId[t] = pock[(size_t)b * NPOCK + t];
    }
    if (t < 45) {
        // 720 contiguous bytes: peptide rows 0..8 only
        ((float4*)sPep)[t] =
            __ldg((const float4*)(pep + (size_t)b * PEP_STRIDE) + t);
    }
    if (t >= 64 && t < 64 + 180) {
        // raw kernel table, row-padded: sKer[row*12 + col] = ker[row*9 + col]
        int i = t - 64;
        sKer[(i / 9) * KER_STRIDE + (i % 9)] = __ldg(ker + i);
    }
    __syncthreads();

    // ---- fused zero+aggregate: every sAgg slot written exactly once ----
    // q: positions = {q%9, 3*(q%3)} dedup'd:
    //   q0:{0} q1:{1,3} q2:{2,6} q3:{0,3} q4:{3,4} q5:{5,6} q6:{0,6} q7:{3,7} q8:{6,8}
    {
        const signed char J0[9] = { 0, 1, 2, 0, 3, 5, 0, 3, 6 };
        const signed char J1[9] = {-1, 3, 6, 3, 4, 6, 6, 7, 8 };
        for (int i = t; i < 9 * AGG_STRIDE; i += 256) {
            int q = i / AGG_STRIDE;
            int s = i - q * AGG_STRIDE;
            int a = s - 8;                 // logical index
            float v = 0.0f;
            if (a >= 0 && a < 20) {
                v = sPep[(int)J0[q] * 20 + a];
                int j1 = J1[q];
                if (j1 >= 0) v += sPep[j1 * 20 + a];
            }
            sAgg[i] = v;
        }
    }
    __syncthreads();

    // ---- convolution: 238 threads, each one float4 of output ----
    if (t < OUT_F4) {
        const int p  = t / 7;           // pocket 0..33
        const int k0 = (t % 7) * 4;     // output k base 0,4,...,24
        const int q  = p % 9;

        // filter row: index raw kernel table by this pocket's amino-acid id
        const int id = sId[p];
        const float* fr = &sKer[id * KER_STRIDE];
        float4 f03 = *(const float4*)(fr + 0);
        float4 f47 = *(const float4*)(fr + 4);
        float  f8v = fr[8];
        float f[9] = { f03.x, f03.y, f03.z, f03.w,
                       f47.x, f47.y, f47.z, f47.w, f8v };

        // a[0..11] = padded aggregate, logical indices k0-8 .. k0+3
        const float* rowp = &sAgg[q * AGG_STRIDE + k0];   // 16B aligned
        float4 a0 = *(const float4*)(rowp + 0);
        float4 a1 = *(const float4*)(rowp + 4);
        float4 a2 = *(const float4*)(rowp + 8);
        float a[12] = { a0.x, a0.y, a0.z, a0.w,
                        a1.x, a1.y, a1.z, a1.w,
                        a2.x, a2.y, a2.z, a2.w };

        float o0 = 0.f, o1 = 0.f, o2 = 0.f, o3 = 0.f;
        #pragma unroll
        for (int j = 0; j < 9; ++j) {
            // out[k] = sum_j f[j] * a_logical[k - j]; reg index = k+8-j
            o0 = fmaf(f[j], a[8  - j], o0);
            o1 = fmaf(f[j], a[9  - j], o1);
            o2 = fmaf(f[j], a[10 - j], o2);
            o3 = fmaf(f[j], a[11 - j], o3);
        }

        ((float4*)out)[(size_t)b * OUT_F4 + t] = make_float4(o0, o1, o2, o3);
    }
}

extern "C" void kernel_launch(void* const* d_in, const int* in_sizes, int n_in,
                              void* d_out, int out_size)
{
    const float* pep  = (const float*)d_in[0];
    const int*   pock = (const int*)d_in[1];
    const float* ker  = (const float*)d_in[2];
    float*       out  = (float*)d_out;

    const int B = in_sizes[1] / NPOCK;   // pocket_encoding is [B, 34]

    pep_pocket_conv_kernel<<<B, 256>>>(pep, pock, ker, out);
}

// round 7
// speedup vs baseline: 2.1933x; 2.1933x over previous
#include <cuda_runtime.h>

// PeptidePocketConvLayer — GB300 sm_103a
//
// Inputs (metadata order):
//   d_in[0]: peptide_encoding  f32 [B, 15, 20]
//   d_in[1]: pocket_encoding   i32 [B, 34]
//   d_in[2]: kernel            f32 [20, 9]
// Output: f32 [B, 34, 28]
//
// Structure exploited:
//  - pocket mask periodic with period 9 -> 9 distinct aggregates/batch
//    agg[q] = pep[q] + (jb != q ? pep[jb] : 0), jb = 3*(q%3)   (closed form)
//  - peptide rows 9..14 never referenced
//  - full conv via zero-padded shared rows (logical indices -8..27)
//  - G=4 batches per block to amortize barriers/launch/guards
//  - conv filter reads: scalar LDS broadcast from pre-gathered sFilt
//    (round-5 lesson: id-indexed vector LDS causes conflict replays)

#define NPOCK      34
#define OUT_F4     238          // 34*28/4 float4 per batch
#define PEP_F4     75           // 15*20/4 float4 per batch (global)
#define AGG_W      36           // padded row words: logical -8..27
#define G          4            // batches per block

__global__ __launch_bounds__(256, 8)
void pep_pocket_conv_kernel(const float* __restrict__ pep,
                            const int*   __restrict__ pock,
                            const float* __restrict__ ker,
                            float*       __restrict__ out)
{
    __shared__ __align__(16) float4 sPepV[G * 45];        // rows 0..8 x 20 per batch
    __shared__ __align__(16) float  sAgg[G * 9 * AGG_W];  // padded agg rows
    __shared__ float sFilt[G * NPOCK * 9];                // gathered filters
    __shared__ int   sId[G * NPOCK];

    const int b0 = blockIdx.x * G;
    const int t  = threadIdx.x;

    // ---- stage: peptide rows 0..8 (45 float4/batch) + pocket ids ----
    if (t < G * 45) {
        int g = t / 45, r = t - g * 45;
        sPepV[t] = __ldg((const float4*)pep + (size_t)(b0 + g) * PEP_F4 + r);
    }
    if (t < G * NPOCK) {
        int g = t / NPOCK, r = t - g * NPOCK;
        sId[t] = pock[(size_t)(b0 + g) * NPOCK + r];
    }
    __syncthreads();

    // ---- gather filters: sFilt[g][p*9+j] = ker[id[g][p]*9 + j] (L1-hot) ----
    for (int i = t; i < G * NPOCK * 9; i += 256) {
        int g = i / (NPOCK * 9), r = i - g * (NPOCK * 9);
        int p = r / 9, j = r - p * 9;
        sFilt[i] = __ldg(ker + sId[g * NPOCK + p] * 9 + j);
    }

    // ---- aggregates, float4-wide; every slot written exactly once ----
    // per batch: 9 rows x 9 f4-slots (slots 0,1,7,8 = zero pad; 2..6 = data)
    for (int s = t; s < G * 81; s += 256) {
        int g = s / 81, r = s - g * 81;
        int q = r / 9,  a = r - q * 9;
        float4 v = make_float4(0.f, 0.f, 0.f, 0.f);
        if (a >= 2 && a <= 6) {
            int c  = a - 2;                      // data f4 index 0..4
            int jb = 3 * (q - 3 * (q / 3));      // 3*(q%3)
            float4 u = sPepV[g * 45 + q * 5 + c];
            if (jb != q) {
                float4 w = sPepV[g * 45 + jb * 5 + c];
                u.x += w.x; u.y += w.y; u.z += w.z; u.w += w.w;
            }
            v = u;
        }
        ((float4*)sAgg)[s] = v;                  // s == g*81 + q*9 + a (36-word rows)
    }
    __syncthreads();

    // ---- convolution: thread t -> float4 (pocket p, k0), for all G batches ----
    if (t < OUT_F4) {
        const int p  = t / 7;
        const int k0 = (t - p * 7) * 4;
        const int q  = p - 9 * (p / 9);          // p % 9
        float4* outV = (float4*)out + (size_t)b0 * OUT_F4 + t;

        #pragma unroll
        for (int g = 0; g < G; ++g) {
            const float* fB   = &sFilt[g * NPOCK * 9 + p * 9];
            const float* rowp = &sAgg[g * 9 * AGG_W + q * AGG_W + k0]; // 16B aligned
            float4 a0 = *(const float4*)(rowp + 0);
            float4 a1 = *(const float4*)(rowp + 4);
            float4 a2 = *(const float4*)(rowp + 8);
            float a[12] = { a0.x, a0.y, a0.z, a0.w,
                            a1.x, a1.y, a1.z, a1.w,
                            a2.x, a2.y, a2.z, a2.w };

            float o0 = 0.f, o1 = 0.f, o2 = 0.f, o3 = 0.f;
            #pragma unroll
            for (int j = 0; j < 9; ++j) {        // out[k] = sum_j f[j]*agg[k-j]
                float fj = fB[j];                // scalar LDS, 7-way broadcast
                o0 = fmaf(fj, a[8  - j], o0);
                o1 = fmaf(fj, a[9  - j], o1);
                o2 = fmaf(fj, a[10 - j], o2);
                o3 = fmaf(fj, a[11 - j], o3);
            }
            outV[g * OUT_F4] = make_float4(o0, o1, o2, o3);
        }
    }
}

extern "C" void kernel_launch(void* const* d_in, const int* in_sizes, int n_in,
                              void* d_out, int out_size)
{
    const float* pep  = (const float*)d_in[0];
    const int*   pock = (const int*)d_in[1];
    const float* ker  = (const float*)d_in[2];
    float*       out  = (float*)d_out;

    const int B = in_sizes[1] / NPOCK;   // pocket_encoding is [B, 34]

    pep_pocket_conv_kernel<<<B / G, 256>>>(pep, pock, ker, out);
}

// round 10
// speedup vs baseline: 2.2627x; 1.0316x over previous
#include <cuda_runtime.h>

// PeptidePocketConvLayer — GB300 sm_103a
//
// Inputs (metadata order):
//   d_in[0]: peptide_encoding  f32 [B, 15, 20]
//   d_in[1]: pocket_encoding   i32 [B, 34]
//   d_in[2]: kernel            f32 [20, 9]
// Output: f32 [B, 34, 28]
//
// Structure exploited:
//  - pocket mask periodic with period 9 -> 9 distinct aggregates/batch
//    agg[q] = pep[q] + (jb != q ? pep[jb] : 0), jb = 3*(q%3)
//  - peptide rows 9..14 never referenced
//  - full conv via zero-padded shared rows (logical indices -8..27)
//  - G=4 batches per block amortizes barriers/launch/guards
//  - filters gathered per pocket into 12-word-padded rows: conv reads a
//    filter row as 2x LDS.128 + 1 scalar (was 9 scalar LDS)
//  - output stored with st.global.cs (write-once stream, evict-first)

#define NPOCK   34
#define OUT_F4  238          // 34*28/4 float4 per batch
#define PEP_F4  75           // 15*20/4 float4 per batch (global)
#define AGG_W   36           // padded agg row words: logical -8..27
#define FSTR    12           // padded filter row words (48B, 16B-aligned)
#define G       4            // batches per block

__global__ __launch_bounds__(256, 8)
void pep_pocket_conv_kernel(const float* __restrict__ pep,
                            const int*   __restrict__ pock,
                            const float* __restrict__ ker,
                            float*       __restrict__ out)
{
    __shared__ __align__(16) float4 sPepV[G * 45];          // rows 0..8 x 20 /batch
    __shared__ __align__(16) float  sAgg[G * 9 * AGG_W];    // padded agg rows
    __shared__ __align__(16) float  sFilt[G * NPOCK * FSTR];// padded filter rows
    __shared__ int sId[G * NPOCK];

    const int b0 = blockIdx.x * G;
    const int t  = threadIdx.x;

    // ---- stage: peptide rows 0..8 (45 f4/batch) + pocket ids ----
    if (t < G * 45) {
        int g = t / 45, r = t - g * 45;
        sPepV[t] = __ldg((const float4*)pep + (size_t)(b0 + g) * PEP_F4 + r);
    }
    if (t < G * NPOCK) {
        int g = t / NPOCK, r = t - g * NPOCK;
        sId[t] = pock[(size_t)(b0 + g) * NPOCK + r];
    }
    __syncthreads();

    // ---- gather filters into padded rows: sFilt[(g*34+p)*12 + j] ----
    for (int i = t; i < G * NPOCK * 9; i += 256) {
        int pp = i / 9, j = i - pp * 9;          // pp = g*34 + p
        sFilt[pp * FSTR + j] = __ldg(ker + sId[pp] * 9 + j);
    }

    // ---- aggregates, float4-wide; every slot written exactly once ----
    // per batch: 9 rows x 9 f4-slots (slots 0,1,7,8 zero pad; 2..6 data)
    for (int s = t; s < G * 81; s += 256) {
        int g = s / 81, r = s - g * 81;
        int q = r / 9,  a = r - q * 9;
        float4 v = make_float4(0.f, 0.f, 0.f, 0.f);
        if (a >= 2 && a <= 6) {
            int c  = a - 2;
            int jb = 3 * (q - 3 * (q / 3));      // 3*(q%3)
            float4 u = sPepV[g * 45 + q * 5 + c];
            if (jb != q) {
                float4 w = sPepV[g * 45 + jb * 5 + c];
                u.x += w.x; u.y += w.y; u.z += w.z; u.w += w.w;
            }
            v = u;
        }
        ((float4*)sAgg)[s] = v;                  // s == g*81 + q*9 + a
    }
    __syncthreads();

    // ---- convolution: thread t -> float4 (pocket p, k0), all G batches ----
    if (t < OUT_F4) {
        const int p  = t / 7;
        const int k0 = (t - p * 7) * 4;
        const int q  = p - 9 * (p / 9);          // p % 9

        const float* fB   = &sFilt[p * FSTR];            // bump by 34*FSTR per g
        const float* rowp = &sAgg[q * AGG_W + k0];       // bump by 9*AGG_W per g
        float4* outV = (float4*)out + (size_t)b0 * OUT_F4 + t;

        #pragma unroll
        for (int g = 0; g < G; ++g) {
            // filter row: 2x LDS.128 + 1 scalar (stride-48B across warp, no conflicts)
            float4 f03 = *(const float4*)(fB + 0);
            float4 f47 = *(const float4*)(fB + 4);
            float  f8v = fB[8];
            float f[9] = { f03.x, f03.y, f03.z, f03.w,
                           f47.x, f47.y, f47.z, f47.w, f8v };

            float4 a0 = *(const float4*)(rowp + 0);
            float4 a1 = *(const float4*)(rowp + 4);
            float4 a2 = *(const float4*)(rowp + 8);
            float a[12] = { a0.x, a0.y, a0.z, a0.w,
                            a1.x, a1.y, a1.z, a1.w,
                            a2.x, a2.y, a2.z, a2.w };

            float o0 = 0.f, o1 = 0.f, o2 = 0.f, o3 = 0.f;
            #pragma unroll
            for (int j = 0; j < 9; ++j) {        // out[k] = sum_j f[j]*agg[k-j]
                o0 = fmaf(f[j], a[8  - j], o0);
                o1 = fmaf(f[j], a[9  - j], o1);
                o2 = fmaf(f[j], a[10 - j], o2);
                o3 = fmaf(f[j], a[11 - j], o3);
            }

            // streaming store: write-once output, evict-first
            __stcs(&outV[g * OUT_F4], make_float4(o0, o1, o2, o3));

            fB   += NPOCK * FSTR;
            rowp += 9 * AGG_W;
        }
    }
}

extern "C" void kernel_launch(void* const* d_in, const int* in_sizes, int n_in,
                              void* d_out, int out_size)
{
    const float* pep  = (const float*)d_in[0];
    const int*   pock = (const int*)d_in[1];
    const float* ker  = (const float*)d_in[2];
    float*       out  = (float*)d_out;

    const int B = in_sizes[1] / NPOCK;   // pocket_encoding is [B, 34]

    pep_pocket_conv_kernel<<<B / G, 256>>>(pep, pock, ker, out);
}